// round 11
// baseline (speedup 1.0000x reference)
#include <cuda_runtime.h>
#include <math.h>
#include <stdint.h>

#define NB   2
#define L    2048
#define H    8
#define D    64
#define HD   512
#define LHD  1048576
#define P    16
#define C    64
#define NC   32
#define EPSF 1e-6f
#define SDT  68

// ---------------- scan-aggregate scratch + flags ----------------
__device__ float g_ks[P*NC*D], g_qs[P*NC*D];   // phase-1 chunk sums (sigmoid k/q)
__device__ float g_ko[P*NC*D], g_qi[P*NC*D];   // phase-2 chunk sums (k*so / q*si)
__device__ float g_eb[P*NC];                   // es chunk sums
__device__ float g_kv[P*NC*D*D];               // KV chunk sums
__device__ int   g_f1[P*NC], g_f2[P*NC], g_f3[P*NC], g_f4[P*NC];

typedef unsigned long long ull;
__device__ __forceinline__ ull pack2(float a, float b){
  ull r; asm("mov.b64 %0, {%1,%2};" : "=l"(r) : "f"(a), "f"(b)); return r;
}
__device__ __forceinline__ void fma2(ull &acc, ull a, ull b){
  asm("fma.rn.f32x2 %0, %1, %2, %0;" : "+l"(acc) : "l"(a), "l"(b));
}
__device__ __forceinline__ ull mul2(ull a, ull b){
  ull r; asm("mul.rn.f32x2 %0, %1, %2;" : "=l"(r) : "l"(a), "l"(b)); return r;
}
__device__ __forceinline__ float2 unpack2(ull v){
  float2 r; asm("mov.b64 {%0,%1}, %2;" : "=f"(r.x), "=f"(r.y) : "l"(v)); return r;
}
__device__ __forceinline__ float sigmoidf_(float x){ return 1.f/(1.f+__expf(-x)); }
__device__ __forceinline__ float f4get(const float4& v, int u){
  return (u==0)?v.x:(u==1)?v.y:(u==2)?v.z:v.w;
}
__device__ __forceinline__ float red4(float v){
  v += __shfl_xor_sync(0xffffffffu, v, 1);
  v += __shfl_xor_sync(0xffffffffu, v, 2);
  return v;
}
// spin until flag != 0 (gpu-scope atomics + backoff)
__device__ __forceinline__ void spin_flag(int* f){
  while(atomicAdd(f, 0) == 0) __nanosleep(40);
}

__global__ void k_reset(){
  int t = threadIdx.x;
  if(t < P*NC){ g_f1[t]=0; g_f2[t]=0; g_f3[t]=0; g_f4[t]=0; }
}

// ---------------- THE fused kernel ----------------
__global__ void __launch_bounds__(256) k_fused(const float* __restrict__ Q,
                                               const float* __restrict__ K,
                                               const float* __restrict__ V,
                                               float* __restrict__ OUT){
  extern __shared__ float sm[];
  float* sqs = sm;             // A: sigmoid(q) [l][d] stride 68; scaled in place later
  float* skT = sm + C*SDT;     // B: sigmoid(k)^T [d][j] stride 68; reused as vss [j][m] s64
  float* STs = sm + 2*C*SDT;   // C: S^T [j][l] stride 68  (STs[j*68+l] = S[l][j])
  float* skr = sm + 3*C*SDT;   // D: sigmoid(k) rows [j][d] s64; reused as kvs [d][m] s64
  float* vss = skT;
  float* kvs = skr;
  __shared__ float rsk[C], rsq[C], b1s[C], b2s[C], sis[C], sos[C];
  __shared__ float kpre[D], qpre[D], kpre2[D], qpre2[D], facs[C], essh[C], sa_s[C], comp[C];
  __shared__ float prefsh, wtot0;

  int c = blockIdx.x, p = blockIdx.y, t = threadIdx.x;
  int pc = p*NC + c;
  const float* Qb = Q + (size_t)(p>>3)*LHD + (size_t)c*C*HD + (size_t)(p&7)*D;
  const float* Kb = K + (size_t)(p>>3)*LHD + (size_t)c*C*HD + (size_t)(p&7)*D;
  const float* Vb = V + (size_t)(p>>3)*LHD + (size_t)c*C*HD + (size_t)(p&7)*D;

  // ---- P1: load Q/K chunk, sigmoid, fill tiles ----
  #pragma unroll
  for(int k=0;k<4;k++){
    int i = t + k*256;
    int row = i>>4, col4 = (i&15)*4;
    float4 q4 = *(const float4*)(Qb + (size_t)row*HD + col4);
    q4.x=sigmoidf_(q4.x); q4.y=sigmoidf_(q4.y); q4.z=sigmoidf_(q4.z); q4.w=sigmoidf_(q4.w);
    *(float4*)(sqs + row*SDT + col4) = q4;
    float4 k4 = *(const float4*)(Kb + (size_t)row*HD + col4);
    k4.x=sigmoidf_(k4.x); k4.y=sigmoidf_(k4.y); k4.z=sigmoidf_(k4.z); k4.w=sigmoidf_(k4.w);
    *(float4*)(skr + row*D + col4) = k4;
    skT[(col4  )*SDT + row] = k4.x;
    skT[(col4+1)*SDT + row] = k4.y;
    skT[(col4+2)*SDT + row] = k4.z;
    skT[(col4+3)*SDT + row] = k4.w;
  }
  __syncthreads();

  int ls = t>>2, gs = t&3;
  // chunk column sums of sk (per d) and sq (per d), publish
  { float a=0.f, b=0.f;
    #pragma unroll
    for(int u=0;u<16;u++){
      int j = 4*u + gs;
      a += skT[ls*SDT + j];        // wait: this is sum over j of skT[d=ls][j] -> ksum[d]
      b += sqs[j*SDT + ls];        // sum over rows j of sq[:, d=ls]  -> qsum[d]
    }
    a = red4(a); b = red4(b);
    if(gs==0){ g_ks[pc*D + ls] = a; g_qs[pc*D + ls] = b; }
  }
  __threadfence(); __syncthreads();
  if(t==0) atomicExch(&g_f1[pc], 1);

  // ---- L1: exclusive prefix of ksum/qsum ----
  if(c > 0){
    if(t < c){ spin_flag(&g_f1[p*NC + t]); __threadfence(); }
    __syncthreads();
    if(t < 64){ float a=0.f; for(int i=0;i<c;i++) a += g_ks[(p*NC+i)*D + t]; kpre[t]=a; }
    else if(t < 128){ int d=t-64; float a=0.f; for(int i=0;i<c;i++) a += g_qs[(p*NC+i)*D + d]; qpre[d]=a; }
  } else {
    if(t < 64) kpre[t]=0.f; else if(t < 128) qpre[t-64]=0.f;
  }
  __syncthreads();

  // ---- Section A: per-l row sums + prefix-base dots ----
  { float rq=0.f, b1=0.f, rk=0.f, b2=0.f;
    #pragma unroll
    for(int u=0;u<4;u++){
      int dd = 16*gs + 4*u;
      float4 q4 = *(const float4*)(sqs + ls*SDT + dd);
      rq += q4.x+q4.y+q4.z+q4.w;
      b1 += (q4.x+EPSF)*(kpre[dd]+EPSF) + (q4.y+EPSF)*(kpre[dd+1]+EPSF)
          + (q4.z+EPSF)*(kpre[dd+2]+EPSF) + (q4.w+EPSF)*(kpre[dd+3]+EPSF);
    }
    #pragma unroll
    for(int u=0;u<16;u++){
      int d = 4*u + gs;
      float kv = skT[d*SDT + ls];
      rk += kv; b2 += (kv+EPSF)*(qpre[d]+EPSF);
    }
    rq = red4(rq); b1 = red4(b1); rk = red4(rk); b2 = red4(b2);
    if(gs==0){ rsq[ls]=rq; b1s[ls]=b1; rsk[ls]=rk; b2s[ls]=b2; }
  }

  // ---- gram: 4l x 4j tiles -> STs (transposed) ----
  int l0 = 4*(t>>4), j0 = 4*(t&15);
  { ull acc[8];
    #pragma unroll
    for(int m=0;m<8;m++) acc[m]=0ull;
    #pragma unroll 4
    for(int dq=0; dq<D; dq+=4){
      float4 q4[4];
      #pragma unroll
      for(int ll=0;ll<4;ll++) q4[ll] = *(const float4*)(sqs + (l0+ll)*SDT + dq);
      #pragma unroll
      for(int du=0;du<4;du++){
        double2 ka = *(const double2*)(skT + (dq+du)*SDT + j0);
        ull k0=(ull)__double_as_longlong(ka.x), k1=(ull)__double_as_longlong(ka.y);
        #pragma unroll
        for(int ll=0;ll<4;ll++){
          float qv = f4get(q4[ll], du);
          ull q2 = pack2(qv,qv);
          fma2(acc[ll*2],   q2, k0);
          fma2(acc[ll*2+1], q2, k1);
        }
      }
    }
    float vals[4][4];
    #pragma unroll
    for(int ll=0;ll<4;ll++){
      float2 a0=unpack2(acc[ll*2]), a1=unpack2(acc[ll*2+1]);
      vals[ll][0]=a0.x; vals[ll][1]=a0.y; vals[ll][2]=a1.x; vals[ll][3]=a1.y;
    }
    #pragma unroll
    for(int jj=0;jj<4;jj++)
      *(float4*)(STs + (j0+jj)*SDT + l0) =
        make_float4(vals[0][jj], vals[1][jj], vals[2][jj], vals[3][jj]);
  }
  __syncthreads();

  // ---- Section B: causal sums -> si/so ----
  { float d1=0.f, d2=0.f;
    for(int i=gs; i<=ls; i+=4){
      d1 += STs[i*SDT + ls] + EPSF*rsk[i];   // S[ls][i]
      d2 += STs[ls*SDT + i] + EPSF*rsq[i];   // S[i][ls]
    }
    d1 = red4(d1); d2 = red4(d2);
    if(gs==0){
      float dot1 = b1s[ls] + d1, dot2 = b2s[ls] + d2;
      float nrm = (float)(c*C + ls + 1);
      sis[ls] = nrm/dot1; sos[ls] = nrm/dot2;
    }
  }
  __syncthreads();

  // ---- Section C: kso/qsi chunk sums, publish ----
  { float a1=0.f, a2=0.f;
    #pragma unroll
    for(int u=0;u<16;u++){
      int j = 4*u + gs;
      a1 += skT[ls*SDT + j]*sos[j];
      a2 += sqs[j*SDT + ls]*sis[j];
    }
    a1 = red4(a1); a2 = red4(a2);
    if(gs==0){ g_ko[pc*D + ls] = a1; g_qi[pc*D + ls] = a2; }
  }
  __threadfence(); __syncthreads();
  if(t==0) atomicExch(&g_f2[pc], 1);

  // ---- L2 ----
  if(c > 0){
    if(t < c){ spin_flag(&g_f2[p*NC + t]); __threadfence(); }
    __syncthreads();
    if(t < 64){ float a=0.f; for(int i=0;i<c;i++) a += g_ko[(p*NC+i)*D + t]; kpre2[t]=a; }
    else if(t < 128){ int d=t-64; float a=0.f; for(int i=0;i<c;i++) a += g_qi[(p*NC+i)*D + d]; qpre2[d]=a; }
  } else {
    if(t < 64) kpre2[t]=0.f; else if(t < 128) qpre2[t-64]=0.f;
  }
  __syncthreads();

  // ---- conserved: sa, es, q-scale factor ----
  { float b3=0.f, b4=0.f;
    #pragma unroll
    for(int u=0;u<4;u++){
      int dd = 16*gs + 4*u;
      float4 q4 = *(const float4*)(sqs + ls*SDT + dd);
      b3 += (q4.x+EPSF)*(kpre2[dd]+EPSF) + (q4.y+EPSF)*(kpre2[dd+1]+EPSF)
          + (q4.z+EPSF)*(kpre2[dd+2]+EPSF) + (q4.w+EPSF)*(kpre2[dd+3]+EPSF);
    }
    #pragma unroll
    for(int u=0;u<16;u++){
      int d = 4*u + gs;
      float kv = skT[d*SDT + ls];
      b4 += (kv+EPSF)*(qpre2[d]+EPSF);
    }
    for(int i=gs; i<=ls; i+=4){
      b3 += sos[i]*(STs[i*SDT + ls] + EPSF*rsk[i]);
      b4 += sis[i]*(STs[ls*SDT + i] + EPSF*rsq[i]);
    }
    b3 = red4(b3); b4 = red4(b4);
    if(gs==0){
      float nrm = (float)(c*C + ls + 1);
      sa_s[ls] = sigmoidf_(b3/nrm);
      float cso = b4/nrm; cso = fminf(1.f, fmaxf(-1.f, cso));
      essh[ls] = __expf(cso);
      facs[ls] = sis[ls]/nrm;
    }
  }
  __syncthreads();

  // scale sqs in place (q_scaled)
  #pragma unroll
  for(int k=0;k<4;k++){
    int i = t + k*256;
    int row = i>>4, col4 = (i&15)*4;
    float4 v = *(const float4*)(sqs + row*SDT + col4);
    float f = facs[row];
    *(float4*)(sqs + row*SDT + col4) = make_float4(v.x*f, v.y*f, v.z*f, v.w*f);
  }
  // publish es chunk sum
  if(t < 32){
    float v = essh[t] + essh[t+32];
    #pragma unroll
    for(int o=16;o;o>>=1) v += __shfl_down_sync(0xffffffffu, v, o);
    if(t==0){ g_eb[pc] = v; __threadfence(); atomicExch(&g_f3[pc], 1); }
  }
  // ---- L3: es prefix ----
  if(c > 0){
    if(t < c){ spin_flag(&g_f3[p*NC + t]); __threadfence(); }
    __syncthreads();
    if(t == 0){ float s=0.f; for(int i=0;i<c;i++) s += g_eb[p*NC+i]; prefsh = s; }
  } else {
    if(t == 0) prefsh = 0.f;
  }
  __syncthreads();
  // comp scan within chunk
  { float xscan = 0.f;
    if(t < 64){
      xscan = essh[t];
      #pragma unroll
      for(int o=1;o<32;o<<=1){
        float y = __shfl_up_sync(0xffffffffu, xscan, o);
        if((t&31) >= o) xscan += y;
      }
      if(t==31) wtot0 = xscan;
    }
    __syncthreads();
    if(t < 64){
      float cum = prefsh + xscan + ((t>=32)? wtot0 : 0.f);
      comp[t] = essh[t]/cum * (float)(c*C + t + 1);
    }
  }
  __syncthreads();

  // ---- vss = V * comp (overwrites skT buffer) ----
  #pragma unroll
  for(int k=0;k<4;k++){
    int i = t + k*256;
    int row = i>>4, col4 = (i&15)*4;
    float4 v = *(const float4*)(Vb + (size_t)row*HD + col4);
    float f = comp[row];
    *(float4*)(vss + row*D + col4) = make_float4(v.x*f, v.y*f, v.z*f, v.w*f);
  }
  __syncthreads();

  // ---- vkv: chunk KV in registers, publish ----
  int d0 = 4*(t>>4), m0 = 4*(t&15);
  { ull acc[8];
    #pragma unroll
    for(int m=0;m<8;m++) acc[m]=0ull;
    #pragma unroll 8
    for(int j=0;j<C;j++){
      float4 sk4 = *(const float4*)(skr + j*D + d0);
      double2 va = *(const double2*)(vss + j*D + m0);
      ull v0=(ull)__double_as_longlong(va.x), v1=(ull)__double_as_longlong(va.y);
      #pragma unroll
      for(int dd=0;dd<4;dd++){
        float a = f4get(sk4, dd);
        ull a2 = pack2(a,a);
        fma2(acc[dd*2],   a2, v0);
        fma2(acc[dd*2+1], a2, v1);
      }
    }
    float* gkv = g_kv + (size_t)pc*D*D;
    #pragma unroll
    for(int dd=0;dd<4;dd++){
      float2 u0=unpack2(acc[dd*2]), u1=unpack2(acc[dd*2+1]);
      *(float4*)(gkv + (d0+dd)*D + m0) = make_float4(u0.x,u0.y,u1.x,u1.y);
    }
  }
  __threadfence(); __syncthreads();
  if(t==0) atomicExch(&g_f4[pc], 1);

  // ---- L4: exclusive KV prefix into kvs (overwrites skr) ----
  if(c > 0){
    if(t < c){ spin_flag(&g_f4[p*NC + t]); __threadfence(); }
    __syncthreads();
    float4 a0=make_float4(0,0,0,0), a1=a0, a2=a0, a3=a0;
    for(int i=0;i<c;i++){
      const float* gkv = g_kv + (size_t)(p*NC+i)*D*D;
      float4 w0 = *(const float4*)(gkv + (d0+0)*D + m0);
      float4 w1 = *(const float4*)(gkv + (d0+1)*D + m0);
      float4 w2 = *(const float4*)(gkv + (d0+2)*D + m0);
      float4 w3 = *(const float4*)(gkv + (d0+3)*D + m0);
      a0.x+=w0.x; a0.y+=w0.y; a0.z+=w0.z; a0.w+=w0.w;
      a1.x+=w1.x; a1.y+=w1.y; a1.z+=w1.z; a1.w+=w1.w;
      a2.x+=w2.x; a2.y+=w2.y; a2.z+=w2.z; a2.w+=w2.w;
      a3.x+=w3.x; a3.y+=w3.y; a3.z+=w3.z; a3.w+=w3.w;
    }
    *(float4*)(kvs + (d0+0)*D + m0) = a0;
    *(float4*)(kvs + (d0+1)*D + m0) = a1;
    *(float4*)(kvs + (d0+2)*D + m0) = a2;
    *(float4*)(kvs + (d0+3)*D + m0) = a3;
  } else {
    for(int i=t;i<D*D;i+=256) kvs[i] = 0.f;
  }
  __syncthreads();

  // ---- out: intra (masked S @ Vs) + inter (q_scaled @ KVprefix) ----
  { ull acc[8];
    #pragma unroll
    for(int m=0;m<8;m++) acc[m]=0ull;
    int nf = l0 >> 2;
    for(int ib=0; ib<nf; ib++){
      float4 st4[4]; double2 va[4];
      #pragma unroll
      for(int u=0;u<4;u++){
        int i = 4*ib+u;
        st4[u] = *(const float4*)(STs + i*SDT + l0);   // S[l0..l0+3][i]
        va[u]  = *(const double2*)(vss + i*D + m0);
      }
      #pragma unroll
      for(int u=0;u<4;u++){
        ull v0=(ull)__double_as_longlong(va[u].x), v1=(ull)__double_as_longlong(va[u].y);
        #pragma unroll
        for(int ll=0;ll<4;ll++){
          float s = f4get(st4[u], ll);
          ull s2 = pack2(s,s);
          fma2(acc[ll*2],   s2, v0);
          fma2(acc[ll*2+1], s2, v1);
        }
      }
    }
    { // masked last group
      float4 st4[4]; double2 va[4];
      #pragma unroll
      for(int u=0;u<4;u++){
        int i = l0+u;
        st4[u] = *(const float4*)(STs + i*SDT + l0);
        va[u]  = *(const double2*)(vss + i*D + m0);
      }
      #pragma unroll
      for(int u=0;u<4;u++){
        ull v0=(ull)__double_as_longlong(va[u].x), v1=(ull)__double_as_longlong(va[u].y);
        #pragma unroll
        for(int ll=0;ll<4;ll++){
          float s = (u <= ll) ? f4get(st4[u], ll) : 0.f;
          ull s2 = pack2(s,s);
          fma2(acc[ll*2],   s2, v0);
          fma2(acc[ll*2+1], s2, v1);
        }
      }
    }
    #pragma unroll
    for(int ll=0;ll<4;ll++){
      float f = facs[l0+ll];           // si/nrm
      ull f2 = pack2(f,f);
      acc[ll*2]   = mul2(acc[ll*2],   f2);
      acc[ll*2+1] = mul2(acc[ll*2+1], f2);
    }
    #pragma unroll 4
    for(int dq=0; dq<D; dq+=4){
      float4 q4[4];
      #pragma unroll
      for(int ll=0;ll<4;ll++) q4[ll] = *(const float4*)(sqs + (l0+ll)*SDT + dq);
      #pragma unroll
      for(int du=0;du<4;du++){
        double2 ka = *(const double2*)(kvs + (dq+du)*D + m0);
        ull k0=(ull)__double_as_longlong(ka.x), k1=(ull)__double_as_longlong(ka.y);
        #pragma unroll
        for(int ll=0;ll<4;ll++){
          float qv = f4get(q4[ll], du);
          ull q2 = pack2(qv,qv);
          fma2(acc[ll*2],   q2, k0);
          fma2(acc[ll*2+1], q2, k1);
        }
      }
    }
    float* op = OUT + (size_t)(p>>3)*LHD + (size_t)c*C*HD + (size_t)(p&7)*D;
    #pragma unroll
    for(int ll=0;ll<4;ll++){
      float sa = sa_s[l0+ll];
      float2 a0=unpack2(acc[ll*2]), a1=unpack2(acc[ll*2+1]);
      *(float4*)(op + (size_t)(l0+ll)*HD + m0) =
        make_float4(a0.x*sa, a0.y*sa, a1.x*sa, a1.y*sa);
    }
  }
}

// ---------------- launch ----------------
extern "C" void kernel_launch(void* const* d_in, const int* in_sizes, int n_in,
                              void* d_out, int out_size){
  const float* Q = (const float*)d_in[0];
  const float* K = (const float*)d_in[1];
  const float* V = (const float*)d_in[2];
  float* OUT = (float*)d_out;

  const int SM_FUSED = (3*C*SDT + C*D)*sizeof(float);   // 68608
  cudaFuncSetAttribute(k_fused, cudaFuncAttributeMaxDynamicSharedMemorySize, SM_FUSED);

  k_reset<<<1, 512>>>();
  k_fused<<<dim3(NC, P), 256, SM_FUSED>>>(Q, K, V, OUT);
}

// round 12
// speedup vs baseline: 1.0532x; 1.0532x over previous
#include <cuda_runtime.h>
#include <math.h>
#include <stdint.h>

#define NB   2
#define L    2048
#define H    8
#define D    64
#define HD   512
#define LHD  1048576
#define P    16
#define C    64
#define NC   32
#define EPSF 1e-6f
#define SDT  68

// ---------------- scan-aggregate scratch + flags ----------------
__device__ float g_ks[P*NC*D], g_qs[P*NC*D];   // phase-1 chunk sums (sigmoid k/q)
__device__ float g_ko[P*NC*D], g_qi[P*NC*D];   // phase-2 chunk sums (k*so / q*si)
__device__ float g_eb[P*NC];                   // es chunk sums
__device__ float g_kv[P*NC*D*D];               // KV chunk sums
__device__ int   g_f1[P*NC], g_f2[P*NC], g_f3[P*NC], g_f4[P*NC];

typedef unsigned long long ull;
__device__ __forceinline__ ull pack2(float a, float b){
  ull r; asm("mov.b64 %0, {%1,%2};" : "=l"(r) : "f"(a), "f"(b)); return r;
}
__device__ __forceinline__ void fma2(ull &acc, ull a, ull b){
  asm("fma.rn.f32x2 %0, %1, %2, %0;" : "+l"(acc) : "l"(a), "l"(b));
}
__device__ __forceinline__ ull mul2(ull a, ull b){
  ull r; asm("mul.rn.f32x2 %0, %1, %2;" : "=l"(r) : "l"(a), "l"(b)); return r;
}
__device__ __forceinline__ float2 unpack2(ull v){
  float2 r; asm("mov.b64 {%0,%1}, %2;" : "=f"(r.x), "=f"(r.y) : "l"(v)); return r;
}
__device__ __forceinline__ float sigmoidf_(float x){ return 1.f/(1.f+__expf(-x)); }
__device__ __forceinline__ float f4get(const float4& v, int u){
  return (u==0)?v.x:(u==1)?v.y:(u==2)?v.z:v.w;
}
__device__ __forceinline__ float red4(float v){
  v += __shfl_xor_sync(0xffffffffu, v, 1);
  v += __shfl_xor_sync(0xffffffffu, v, 2);
  return v;
}
// acquire-load poll (plain LTS load, NOT an atomic — no LTS-ALU serialization)
__device__ __forceinline__ int ld_acq(const int* p){
  int v; asm volatile("ld.global.acquire.gpu.b32 %0, [%1];" : "=r"(v) : "l"(p)); return v;
}
__device__ __forceinline__ void spin_flag(const int* f){
  int it = 0;
  while(ld_acq(f) == 0){
    __nanosleep(it < 8 ? 64 : 512);
    it++;
  }
}

__global__ void k_reset(){
  int t = threadIdx.x;
  if(t < P*NC){ g_f1[t]=0; g_f2[t]=0; g_f3[t]=0; g_f4[t]=0; }
}

// ---------------- THE fused kernel ----------------
__global__ void __launch_bounds__(256,3) k_fused(const float* __restrict__ Q,
                                                 const float* __restrict__ K,
                                                 const float* __restrict__ V,
                                                 float* __restrict__ OUT){
  extern __shared__ float sm[];
  float* sqs = sm;             // A: sigmoid(q) [l][d] stride 68; scaled in place later
  float* skT = sm + C*SDT;     // B: sigmoid(k)^T [d][j] stride 68; reused as vss [j][m] s64
  float* STs = sm + 2*C*SDT;   // C: S^T [j][l] stride 68  (STs[j*68+l] = S[l][j])
  float* skr = sm + 3*C*SDT;   // D: sigmoid(k) rows [j][d] s64; reused as kvs [d][m] s64
  float* vss = skT;
  float* kvs = skr;
  __shared__ float rsk[C], rsq[C], b1s[C], b2s[C], sis[C], sos[C];
  __shared__ float kpre[D], qpre[D], kpre2[D], qpre2[D], facs[C], essh[C], sa_s[C], comp[C];
  __shared__ float prefsh, wtot0;

  int c = blockIdx.x, p = blockIdx.y, t = threadIdx.x;
  int pc = p*NC + c;
  const float* Qb = Q + (size_t)(p>>3)*LHD + (size_t)c*C*HD + (size_t)(p&7)*D;
  const float* Kb = K + (size_t)(p>>3)*LHD + (size_t)c*C*HD + (size_t)(p&7)*D;
  const float* Vb = V + (size_t)(p>>3)*LHD + (size_t)c*C*HD + (size_t)(p&7)*D;

  // ---- P1: load Q/K chunk, sigmoid, fill tiles ----
  #pragma unroll
  for(int k=0;k<4;k++){
    int i = t + k*256;
    int row = i>>4, col4 = (i&15)*4;
    float4 q4 = *(const float4*)(Qb + (size_t)row*HD + col4);
    q4.x=sigmoidf_(q4.x); q4.y=sigmoidf_(q4.y); q4.z=sigmoidf_(q4.z); q4.w=sigmoidf_(q4.w);
    *(float4*)(sqs + row*SDT + col4) = q4;
    float4 k4 = *(const float4*)(Kb + (size_t)row*HD + col4);
    k4.x=sigmoidf_(k4.x); k4.y=sigmoidf_(k4.y); k4.z=sigmoidf_(k4.z); k4.w=sigmoidf_(k4.w);
    *(float4*)(skr + row*D + col4) = k4;
    skT[(col4  )*SDT + row] = k4.x;
    skT[(col4+1)*SDT + row] = k4.y;
    skT[(col4+2)*SDT + row] = k4.z;
    skT[(col4+3)*SDT + row] = k4.w;
  }
  __syncthreads();

  int ls = t>>2, gs = t&3;
  // chunk sums per d, publish
  { float a=0.f, b=0.f;
    #pragma unroll
    for(int u=0;u<16;u++){
      int j = 4*u + gs;
      a += skT[ls*SDT + j];
      b += sqs[j*SDT + ls];
    }
    a = red4(a); b = red4(b);
    if(gs==0){ g_ks[pc*D + ls] = a; g_qs[pc*D + ls] = b; }
  }
  __threadfence(); __syncthreads();
  if(t==0) atomicExch(&g_f1[pc], 1);

  // ---- L1: exclusive prefix of ksum/qsum ----
  if(c > 0){
    if(t < c) spin_flag(&g_f1[p*NC + t]);
    __syncthreads();
    if(t < 64){ float a=0.f; for(int i=0;i<c;i++) a += __ldg(&g_ks[(p*NC+i)*D + t]); kpre[t]=a; }
    else if(t < 128){ int d=t-64; float a=0.f; for(int i=0;i<c;i++) a += __ldg(&g_qs[(p*NC+i)*D + d]); qpre[d]=a; }
  } else {
    if(t < 64) kpre[t]=0.f; else if(t < 128) qpre[t-64]=0.f;
  }
  __syncthreads();

  // ---- Section A: per-l row sums + prefix-base dots ----
  { float rq=0.f, b1=0.f, rk=0.f, b2=0.f;
    #pragma unroll
    for(int u=0;u<4;u++){
      int dd = 16*gs + 4*u;
      float4 q4 = *(const float4*)(sqs + ls*SDT + dd);
      rq += q4.x+q4.y+q4.z+q4.w;
      b1 += (q4.x+EPSF)*(kpre[dd]+EPSF) + (q4.y+EPSF)*(kpre[dd+1]+EPSF)
          + (q4.z+EPSF)*(kpre[dd+2]+EPSF) + (q4.w+EPSF)*(kpre[dd+3]+EPSF);
    }
    #pragma unroll
    for(int u=0;u<16;u++){
      int d = 4*u + gs;
      float kv = skT[d*SDT + ls];
      rk += kv; b2 += (kv+EPSF)*(qpre[d]+EPSF);
    }
    rq = red4(rq); b1 = red4(b1); rk = red4(rk); b2 = red4(b2);
    if(gs==0){ rsq[ls]=rq; b1s[ls]=b1; rsk[ls]=rk; b2s[ls]=b2; }
  }

  // ---- gram: 4l x 4j tiles -> STs (transposed) ----
  int l0 = 4*(t>>4), j0 = 4*(t&15);
  { ull acc[8];
    #pragma unroll
    for(int m=0;m<8;m++) acc[m]=0ull;
    #pragma unroll 4
    for(int dq=0; dq<D; dq+=4){
      float4 q4[4];
      #pragma unroll
      for(int ll=0;ll<4;ll++) q4[ll] = *(const float4*)(sqs + (l0+ll)*SDT + dq);
      #pragma unroll
      for(int du=0;du<4;du++){
        double2 ka = *(const double2*)(skT + (dq+du)*SDT + j0);
        ull k0=(ull)__double_as_longlong(ka.x), k1=(ull)__double_as_longlong(ka.y);
        #pragma unroll
        for(int ll=0;ll<4;ll++){
          float qv = f4get(q4[ll], du);
          ull q2 = pack2(qv,qv);
          fma2(acc[ll*2],   q2, k0);
          fma2(acc[ll*2+1], q2, k1);
        }
      }
    }
    float vals[4][4];
    #pragma unroll
    for(int ll=0;ll<4;ll++){
      float2 a0=unpack2(acc[ll*2]), a1=unpack2(acc[ll*2+1]);
      vals[ll][0]=a0.x; vals[ll][1]=a0.y; vals[ll][2]=a1.x; vals[ll][3]=a1.y;
    }
    #pragma unroll
    for(int jj=0;jj<4;jj++)
      *(float4*)(STs + (j0+jj)*SDT + l0) =
        make_float4(vals[0][jj], vals[1][jj], vals[2][jj], vals[3][jj]);
  }
  __syncthreads();

  // ---- Section B: causal sums -> si/so ----
  { float d1=0.f, d2=0.f;
    for(int i=gs; i<=ls; i+=4){
      d1 += STs[i*SDT + ls] + EPSF*rsk[i];   // S[ls][i]
      d2 += STs[ls*SDT + i] + EPSF*rsq[i];   // S[i][ls]
    }
    d1 = red4(d1); d2 = red4(d2);
    if(gs==0){
      float dot1 = b1s[ls] + d1, dot2 = b2s[ls] + d2;
      float nrm = (float)(c*C + ls + 1);
      sis[ls] = nrm/dot1; sos[ls] = nrm/dot2;
    }
  }
  __syncthreads();

  // ---- Section C: kso/qsi chunk sums, publish ----
  { float a1=0.f, a2=0.f;
    #pragma unroll
    for(int u=0;u<16;u++){
      int j = 4*u + gs;
      a1 += skT[ls*SDT + j]*sos[j];
      a2 += sqs[j*SDT + ls]*sis[j];
    }
    a1 = red4(a1); a2 = red4(a2);
    if(gs==0){ g_ko[pc*D + ls] = a1; g_qi[pc*D + ls] = a2; }
  }
  __threadfence(); __syncthreads();
  if(t==0) atomicExch(&g_f2[pc], 1);

  // ---- L2 ----
  if(c > 0){
    if(t < c) spin_flag(&g_f2[p*NC + t]);
    __syncthreads();
    if(t < 64){ float a=0.f; for(int i=0;i<c;i++) a += __ldg(&g_ko[(p*NC+i)*D + t]); kpre2[t]=a; }
    else if(t < 128){ int d=t-64; float a=0.f; for(int i=0;i<c;i++) a += __ldg(&g_qi[(p*NC+i)*D + d]); qpre2[d]=a; }
  } else {
    if(t < 64) kpre2[t]=0.f; else if(t < 128) qpre2[t-64]=0.f;
  }
  __syncthreads();

  // ---- conserved: sa, es, q-scale factor ----
  { float b3=0.f, b4=0.f;
    #pragma unroll
    for(int u=0;u<4;u++){
      int dd = 16*gs + 4*u;
      float4 q4 = *(const float4*)(sqs + ls*SDT + dd);
      b3 += (q4.x+EPSF)*(kpre2[dd]+EPSF) + (q4.y+EPSF)*(kpre2[dd+1]+EPSF)
          + (q4.z+EPSF)*(kpre2[dd+2]+EPSF) + (q4.w+EPSF)*(kpre2[dd+3]+EPSF);
    }
    #pragma unroll
    for(int u=0;u<16;u++){
      int d = 4*u + gs;
      float kv = skT[d*SDT + ls];
      b4 += (kv+EPSF)*(qpre2[d]+EPSF);
    }
    for(int i=gs; i<=ls; i+=4){
      b3 += sos[i]*(STs[i*SDT + ls] + EPSF*rsk[i]);
      b4 += sis[i]*(STs[ls*SDT + i] + EPSF*rsq[i]);
    }
    b3 = red4(b3); b4 = red4(b4);
    if(gs==0){
      float nrm = (float)(c*C + ls + 1);
      sa_s[ls] = sigmoidf_(b3/nrm);
      float cso = b4/nrm; cso = fminf(1.f, fmaxf(-1.f, cso));
      essh[ls] = __expf(cso);
      facs[ls] = sis[ls]/nrm;
    }
  }
  __syncthreads();

  // scale sqs in place (q_scaled)
  #pragma unroll
  for(int k=0;k<4;k++){
    int i = t + k*256;
    int row = i>>4, col4 = (i&15)*4;
    float4 v = *(const float4*)(sqs + row*SDT + col4);
    float f = facs[row];
    *(float4*)(sqs + row*SDT + col4) = make_float4(v.x*f, v.y*f, v.z*f, v.w*f);
  }
  // publish es chunk sum
  if(t < 32){
    float v = essh[t] + essh[t+32];
    #pragma unroll
    for(int o=16;o;o>>=1) v += __shfl_down_sync(0xffffffffu, v, o);
    if(t==0){ g_eb[pc] = v; __threadfence(); atomicExch(&g_f3[pc], 1); }
  }
  // ---- L3: es prefix ----
  if(c > 0){
    if(t < c) spin_flag(&g_f3[p*NC + t]);
    __syncthreads();
    if(t == 0){ float s=0.f; for(int i=0;i<c;i++) s += __ldg(&g_eb[p*NC+i]); prefsh = s; }
  } else {
    if(t == 0) prefsh = 0.f;
  }
  __syncthreads();
  // comp scan within chunk
  { float xscan = 0.f;
    if(t < 64){
      xscan = essh[t];
      #pragma unroll
      for(int o=1;o<32;o<<=1){
        float y = __shfl_up_sync(0xffffffffu, xscan, o);
        if((t&31) >= o) xscan += y;
      }
      if(t==31) wtot0 = xscan;
    }
    __syncthreads();
    if(t < 64){
      float cum = prefsh + xscan + ((t>=32)? wtot0 : 0.f);
      comp[t] = essh[t]/cum * (float)(c*C + t + 1);
    }
  }
  __syncthreads();

  // ---- vss = V * comp (overwrites skT buffer) ----
  #pragma unroll
  for(int k=0;k<4;k++){
    int i = t + k*256;
    int row = i>>4, col4 = (i&15)*4;
    float4 v = *(const float4*)(Vb + (size_t)row*HD + col4);
    float f = comp[row];
    *(float4*)(vss + row*D + col4) = make_float4(v.x*f, v.y*f, v.z*f, v.w*f);
  }
  __syncthreads();

  // ---- vkv: chunk KV in registers, publish ----
  int d0 = 4*(t>>4), m0 = 4*(t&15);
  { ull acc[8];
    #pragma unroll
    for(int m=0;m<8;m++) acc[m]=0ull;
    #pragma unroll 8
    for(int j=0;j<C;j++){
      float4 sk4 = *(const float4*)(skr + j*D + d0);
      double2 va = *(const double2*)(vss + j*D + m0);
      ull v0=(ull)__double_as_longlong(va.x), v1=(ull)__double_as_longlong(va.y);
      #pragma unroll
      for(int dd=0;dd<4;dd++){
        float a = f4get(sk4, dd);
        ull a2 = pack2(a,a);
        fma2(acc[dd*2],   a2, v0);
        fma2(acc[dd*2+1], a2, v1);
      }
    }
    float* gkv = g_kv + (size_t)pc*D*D;
    #pragma unroll
    for(int dd=0;dd<4;dd++){
      float2 u0=unpack2(acc[dd*2]), u1=unpack2(acc[dd*2+1]);
      *(float4*)(gkv + (d0+dd)*D + m0) = make_float4(u0.x,u0.y,u1.x,u1.y);
    }
  }
  __threadfence(); __syncthreads();
  if(t==0) atomicExch(&g_f4[pc], 1);

  // ---- L4: exclusive KV prefix into kvs (overwrites skr) ----
  if(c > 0){
    if(t < c) spin_flag(&g_f4[p*NC + t]);
    __syncthreads();
    float4 a0=make_float4(0,0,0,0), a1=a0, a2=a0, a3=a0;
    for(int i=0;i<c;i++){
      const float4* gkv = (const float4*)(g_kv + (size_t)(p*NC+i)*D*D);
      float4 w0 = __ldg(gkv + ((d0+0)*D + m0)/4);
      float4 w1 = __ldg(gkv + ((d0+1)*D + m0)/4);
      float4 w2 = __ldg(gkv + ((d0+2)*D + m0)/4);
      float4 w3 = __ldg(gkv + ((d0+3)*D + m0)/4);
      a0.x+=w0.x; a0.y+=w0.y; a0.z+=w0.z; a0.w+=w0.w;
      a1.x+=w1.x; a1.y+=w1.y; a1.z+=w1.z; a1.w+=w1.w;
      a2.x+=w2.x; a2.y+=w2.y; a2.z+=w2.z; a2.w+=w2.w;
      a3.x+=w3.x; a3.y+=w3.y; a3.z+=w3.z; a3.w+=w3.w;
    }
    *(float4*)(kvs + (d0+0)*D + m0) = a0;
    *(float4*)(kvs + (d0+1)*D + m0) = a1;
    *(float4*)(kvs + (d0+2)*D + m0) = a2;
    *(float4*)(kvs + (d0+3)*D + m0) = a3;
  } else {
    for(int i=t;i<D*D;i+=256) kvs[i] = 0.f;
  }
  __syncthreads();

  // ---- out: intra (masked S @ Vs) + inter (q_scaled @ KVprefix) ----
  { ull acc[8];
    #pragma unroll
    for(int m=0;m<8;m++) acc[m]=0ull;
    int nf = l0 >> 2;
    for(int ib=0; ib<nf; ib++){
      float4 st4[4]; double2 va[4];
      #pragma unroll
      for(int u=0;u<4;u++){
        int i = 4*ib+u;
        st4[u] = *(const float4*)(STs + i*SDT + l0);
        va[u]  = *(const double2*)(vss + i*D + m0);
      }
      #pragma unroll
      for(int u=0;u<4;u++){
        ull v0=(ull)__double_as_longlong(va[u].x), v1=(ull)__double_as_longlong(va[u].y);
        #pragma unroll
        for(int ll=0;ll<4;ll++){
          float s = f4get(st4[u], ll);
          ull s2 = pack2(s,s);
          fma2(acc[ll*2],   s2, v0);
          fma2(acc[ll*2+1], s2, v1);
        }
      }
    }
    { float4 st4[4]; double2 va[4];
      #pragma unroll
      for(int u=0;u<4;u++){
        int i = l0+u;
        st4[u] = *(const float4*)(STs + i*SDT + l0);
        va[u]  = *(const double2*)(vss + i*D + m0);
      }
      #pragma unroll
      for(int u=0;u<4;u++){
        ull v0=(ull)__double_as_longlong(va[u].x), v1=(ull)__double_as_longlong(va[u].y);
        #pragma unroll
        for(int ll=0;ll<4;ll++){
          float s = (u <= ll) ? f4get(st4[u], ll) : 0.f;
          ull s2 = pack2(s,s);
          fma2(acc[ll*2],   s2, v0);
          fma2(acc[ll*2+1], s2, v1);
        }
      }
    }
    #pragma unroll
    for(int ll=0;ll<4;ll++){
      float f = facs[l0+ll];
      ull f2 = pack2(f,f);
      acc[ll*2]   = mul2(acc[ll*2],   f2);
      acc[ll*2+1] = mul2(acc[ll*2+1], f2);
    }
    #pragma unroll 4
    for(int dq=0; dq<D; dq+=4){
      float4 q4[4];
      #pragma unroll
      for(int ll=0;ll<4;ll++) q4[ll] = *(const float4*)(sqs + (l0+ll)*SDT + dq);
      #pragma unroll
      for(int du=0;du<4;du++){
        double2 ka = *(const double2*)(kvs + (dq+du)*D + m0);
        ull k0=(ull)__double_as_longlong(ka.x), k1=(ull)__double_as_longlong(ka.y);
        #pragma unroll
        for(int ll=0;ll<4;ll++){
          float qv = f4get(q4[ll], du);
          ull q2 = pack2(qv,qv);
          fma2(acc[ll*2],   q2, k0);
          fma2(acc[ll*2+1], q2, k1);
        }
      }
    }
    float* op = OUT + (size_t)(p>>3)*LHD + (size_t)c*C*HD + (size_t)(p&7)*D;
    #pragma unroll
    for(int ll=0;ll<4;ll++){
      float sa = sa_s[l0+ll];
      float2 a0=unpack2(acc[ll*2]), a1=unpack2(acc[ll*2+1]);
      *(float4*)(op + (size_t)(l0+ll)*HD + m0) =
        make_float4(a0.x*sa, a0.y*sa, a1.x*sa, a1.y*sa);
    }
  }
}

// ---------------- launch ----------------
extern "C" void kernel_launch(void* const* d_in, const int* in_sizes, int n_in,
                              void* d_out, int out_size){
  const float* Q = (const float*)d_in[0];
  const float* K = (const float*)d_in[1];
  const float* V = (const float*)d_in[2];
  float* OUT = (float*)d_out;

  const int SM_FUSED = (3*C*SDT + C*D)*sizeof(float);   // 68608
  cudaFuncSetAttribute(k_fused, cudaFuncAttributeMaxDynamicSharedMemorySize, SM_FUSED);

  k_reset<<<1, 512>>>();
  k_fused<<<dim3(NC, P), 256, SM_FUSED>>>(Q, K, V, OUT);
}

// round 14
// speedup vs baseline: 1.1200x; 1.0634x over previous
#include <cuda_runtime.h>
#include <math.h>
#include <stdint.h>

#define NB   2
#define L    2048
#define H    8
#define D    64
#define HD   512
#define LHD  1048576
#define P    16
#define C    64
#define NC   32
#define EPSF 1e-6f
#define SDT  68

// ---------------- scan-aggregate scratch + flags ----------------
__device__ float g_ks[P*NC*D], g_qs[P*NC*D];   // phase-1 chunk sums (sigmoid k/q)
__device__ float g_ko[P*NC*D], g_qi[P*NC*D];   // phase-2 chunk sums (k*so / q*si)
__device__ float g_eb[P*NC];                   // es chunk sums
__device__ float g_kv[P*NC*D*D];               // KV chunk sums
__device__ int   g_f1[P*NC], g_f2[P*NC], g_f3[P*NC], g_f4[P*NC];

typedef unsigned long long ull;
__device__ __forceinline__ ull pack2(float a, float b){
  ull r; asm("mov.b64 %0, {%1,%2};" : "=l"(r) : "f"(a), "f"(b)); return r;
}
__device__ __forceinline__ void fma2(ull &acc, ull a, ull b){
  asm("fma.rn.f32x2 %0, %1, %2, %0;" : "+l"(acc) : "l"(a), "l"(b));
}
__device__ __forceinline__ ull mul2(ull a, ull b){
  ull r; asm("mul.rn.f32x2 %0, %1, %2;" : "=l"(r) : "l"(a), "l"(b)); return r;
}
__device__ __forceinline__ float2 unpack2(ull v){
  float2 r; asm("mov.b64 {%0,%1}, %2;" : "=f"(r.x), "=f"(r.y) : "l"(v)); return r;
}
__device__ __forceinline__ float sigmoidf_(float x){ return 1.f/(1.f+__expf(-x)); }
__device__ __forceinline__ float f4get(const float4& v, int u){
  return (u==0)?v.x:(u==1)?v.y:(u==2)?v.z:v.w;
}
__device__ __forceinline__ float red4(float v){
  v += __shfl_xor_sync(0xffffffffu, v, 1);
  v += __shfl_xor_sync(0xffffffffu, v, 2);
  return v;
}
__device__ __forceinline__ int ld_acq(const int* p){
  int v; asm volatile("ld.global.acquire.gpu.b32 %0, [%1];" : "=r"(v) : "l"(p)); return v;
}
__device__ __forceinline__ void spin_flag(const int* f){
  int it = 0;
  while(ld_acq(f) == 0){
    __nanosleep(it < 16 ? 32 : 256);
    it++;
  }
}

__global__ void k_reset(){
  int t = threadIdx.x;
  if(t < P*NC){ g_f1[t]=0; g_f2[t]=0; g_f3[t]=0; g_f4[t]=0; }
}

// ---------------- THE fused kernel (reordered to hide waits) ----------------
__global__ void __launch_bounds__(256,3) k_fused(const float* __restrict__ Q,
                                                 const float* __restrict__ K,
                                                 const float* __restrict__ V,
                                                 float* __restrict__ OUT){
  extern __shared__ float sm[];
  float* sqs = sm;             // sigmoid(q) [l][d] stride 68; scaled in place later
  float* skT = sm + C*SDT;     // sigmoid(k)^T [d][j] stride 68; reused as vss [j][m] s64
  float* STs = sm + 2*C*SDT;   // S^T [j][l] stride 68  (STs[j*68+l] = S[l][j])
  float* skr = sm + 3*C*SDT;   // sigmoid(k) rows [j][d] s64; reused as kvs [d][m] s64
  float* vss = skT;
  float* kvs = skr;
  __shared__ float rsk[C], rsq[C], d1s[C], d2s[C], b3c[C], b4c[C], sis[C], sos[C];
  __shared__ float kpre[D], qpre[D], kpre2[D], qpre2[D], facs[C], essh[C], sa_s[C], comp[C];
  __shared__ float prefsh, wtot0;

  int c = blockIdx.x, p = blockIdx.y, t = threadIdx.x;
  int pc = p*NC + c;
  const float* Qb = Q + (size_t)(p>>3)*LHD + (size_t)c*C*HD + (size_t)(p&7)*D;
  const float* Kb = K + (size_t)(p>>3)*LHD + (size_t)c*C*HD + (size_t)(p&7)*D;
  const float* Vb = V + (size_t)(p>>3)*LHD + (size_t)c*C*HD + (size_t)(p&7)*D;

  // ---- load tiles, sigmoid ----
  #pragma unroll
  for(int k=0;k<4;k++){
    int i = t + k*256;
    int row = i>>4, col4 = (i&15)*4;
    float4 q4 = *(const float4*)(Qb + (size_t)row*HD + col4);
    q4.x=sigmoidf_(q4.x); q4.y=sigmoidf_(q4.y); q4.z=sigmoidf_(q4.z); q4.w=sigmoidf_(q4.w);
    *(float4*)(sqs + row*SDT + col4) = q4;
    float4 k4 = *(const float4*)(Kb + (size_t)row*HD + col4);
    k4.x=sigmoidf_(k4.x); k4.y=sigmoidf_(k4.y); k4.z=sigmoidf_(k4.z); k4.w=sigmoidf_(k4.w);
    *(float4*)(skr + row*D + col4) = k4;
    skT[(col4  )*SDT + row] = k4.x;
    skT[(col4+1)*SDT + row] = k4.y;
    skT[(col4+2)*SDT + row] = k4.z;
    skT[(col4+3)*SDT + row] = k4.w;
  }
  __syncthreads();

  int ls = t>>2, gs = t&3;
  // ---- chunk sums, publish f1 EARLY ----
  { float a=0.f, b=0.f;
    #pragma unroll
    for(int u=0;u<16;u++){
      int j = 4*u + gs;
      a += skT[ls*SDT + j];
      b += sqs[j*SDT + ls];
    }
    a = red4(a); b = red4(b);
    if(gs==0){ g_ks[pc*D + ls] = a; g_qs[pc*D + ls] = b; }
  }
  __threadfence(); __syncthreads();
  if(t==0) atomicExch(&g_f1[pc], 1);

  // ---- row sums rsk/rsq (prefix-independent) ----
  { float rk=0.f, rq=0.f;
    #pragma unroll
    for(int u=0;u<16;u++){
      int d = 4*u + gs;
      rk += skT[d*SDT + ls];
    }
    #pragma unroll
    for(int u=0;u<4;u++){
      int dd = 16*gs + 4*u;
      float4 q4 = *(const float4*)(sqs + ls*SDT + dd);
      rq += q4.x+q4.y+q4.z+q4.w;
    }
    rk = red4(rk); rq = red4(rq);
    if(gs==0){ rsk[ls]=rk; rsq[ls]=rq; }
  }

  // ---- gram: 4l x 4j tiles -> STs (prefix-independent) ----
  int l0 = 4*(t>>4), j0 = 4*(t&15);
  { ull acc[8];
    #pragma unroll
    for(int m=0;m<8;m++) acc[m]=0ull;
    #pragma unroll 4
    for(int dq=0; dq<D; dq+=4){
      float4 q4[4];
      #pragma unroll
      for(int ll=0;ll<4;ll++) q4[ll] = *(const float4*)(sqs + (l0+ll)*SDT + dq);
      #pragma unroll
      for(int du=0;du<4;du++){
        double2 ka = *(const double2*)(skT + (dq+du)*SDT + j0);
        ull k0=(ull)__double_as_longlong(ka.x), k1=(ull)__double_as_longlong(ka.y);
        #pragma unroll
        for(int ll=0;ll<4;ll++){
          float qv = f4get(q4[ll], du);
          ull q2 = pack2(qv,qv);
          fma2(acc[ll*2],   q2, k0);
          fma2(acc[ll*2+1], q2, k1);
        }
      }
    }
    float vals[4][4];
    #pragma unroll
    for(int ll=0;ll<4;ll++){
      float2 a0=unpack2(acc[ll*2]), a1=unpack2(acc[ll*2+1]);
      vals[ll][0]=a0.x; vals[ll][1]=a0.y; vals[ll][2]=a1.x; vals[ll][3]=a1.y;
    }
    #pragma unroll
    for(int jj=0;jj<4;jj++)
      *(float4*)(STs + (j0+jj)*SDT + l0) =
        make_float4(vals[0][jj], vals[1][jj], vals[2][jj], vals[3][jj]);
  }
  __syncthreads();

  // ---- causal sums of S (prefix-independent) ----
  { float d1=0.f, d2=0.f;
    for(int i=gs; i<=ls; i+=4){
      d1 += STs[i*SDT + ls] + EPSF*rsk[i];   // S[ls][i]
      d2 += STs[ls*SDT + i] + EPSF*rsq[i];   // S[i][ls]
    }
    d1 = red4(d1); d2 = red4(d2);
    if(gs==0){ d1s[ls]=d1; d2s[ls]=d2; }
  }

  // ---- L1 wait (now overlapped by gram+causal above) ----
  if(c > 0){
    if(t < c) spin_flag(&g_f1[p*NC + t]);
    __syncthreads();
    if(t < 64){ float a=0.f; for(int i=0;i<c;i++) a += __ldg(&g_ks[(p*NC+i)*D + t]); kpre[t]=a; }
    else if(t < 128){ int d=t-64; float a=0.f; for(int i=0;i<c;i++) a += __ldg(&g_qs[(p*NC+i)*D + d]); qpre[d]=a; }
  } else {
    if(t < 64) kpre[t]=0.f; else if(t < 128) qpre[t-64]=0.f;
  }
  __syncthreads();

  // ---- b1/b2 prefix dots -> si/so ----
  { float b1=0.f, b2=0.f;
    #pragma unroll
    for(int u=0;u<4;u++){
      int dd = 16*gs + 4*u;
      float4 q4 = *(const float4*)(sqs + ls*SDT + dd);
      b1 += (q4.x+EPSF)*(kpre[dd]+EPSF) + (q4.y+EPSF)*(kpre[dd+1]+EPSF)
          + (q4.z+EPSF)*(kpre[dd+2]+EPSF) + (q4.w+EPSF)*(kpre[dd+3]+EPSF);
    }
    #pragma unroll
    for(int u=0;u<16;u++){
      int d = 4*u + gs;
      float kv = skT[d*SDT + ls];
      b2 += (kv+EPSF)*(qpre[d]+EPSF);
    }
    b1 = red4(b1); b2 = red4(b2);
    if(gs==0){
      float nrm = (float)(c*C + ls + 1);
      sis[ls] = nrm/(b1 + d1s[ls]);
      sos[ls] = nrm/(b2 + d2s[ls]);
    }
  }
  __syncthreads();

  // ---- kso/qsi chunk sums, publish f2 ----
  { float a1=0.f, a2=0.f;
    #pragma unroll
    for(int u=0;u<16;u++){
      int j = 4*u + gs;
      a1 += skT[ls*SDT + j]*sos[j];
      a2 += sqs[j*SDT + ls]*sis[j];
    }
    a1 = red4(a1); a2 = red4(a2);
    if(gs==0){ g_ko[pc*D + ls] = a1; g_qi[pc*D + ls] = a2; }
  }
  __threadfence(); __syncthreads();
  if(t==0) atomicExch(&g_f2[pc], 1);

  // ---- conserved causal partials (prefix-independent; hides L2) ----
  { float b3=0.f, b4=0.f;
    for(int i=gs; i<=ls; i+=4){
      b3 += sos[i]*(STs[i*SDT + ls] + EPSF*rsk[i]);
      b4 += sis[i]*(STs[ls*SDT + i] + EPSF*rsq[i]);
    }
    b3 = red4(b3); b4 = red4(b4);
    if(gs==0){ b3c[ls]=b3; b4c[ls]=b4; }
  }

  // ---- L2 wait ----
  if(c > 0){
    if(t < c) spin_flag(&g_f2[p*NC + t]);
    __syncthreads();
    if(t < 64){ float a=0.f; for(int i=0;i<c;i++) a += __ldg(&g_ko[(p*NC+i)*D + t]); kpre2[t]=a; }
    else if(t < 128){ int d=t-64; float a=0.f; for(int i=0;i<c;i++) a += __ldg(&g_qi[(p*NC+i)*D + d]); qpre2[d]=a; }
  } else {
    if(t < 64) kpre2[t]=0.f; else if(t < 128) qpre2[t-64]=0.f;
  }
  __syncthreads();

  // ---- finish conserved: sa, es, q-scale factor ----
  { float b3=0.f, b4=0.f;
    #pragma unroll
    for(int u=0;u<4;u++){
      int dd = 16*gs + 4*u;
      float4 q4 = *(const float4*)(sqs + ls*SDT + dd);
      b3 += (q4.x+EPSF)*(kpre2[dd]+EPSF) + (q4.y+EPSF)*(kpre2[dd+1]+EPSF)
          + (q4.z+EPSF)*(kpre2[dd+2]+EPSF) + (q4.w+EPSF)*(kpre2[dd+3]+EPSF);
    }
    #pragma unroll
    for(int u=0;u<16;u++){
      int d = 4*u + gs;
      float kv = skT[d*SDT + ls];
      b4 += (kv+EPSF)*(qpre2[d]+EPSF);
    }
    b3 = red4(b3); b4 = red4(b4);
    if(gs==0){
      b3 += b3c[ls]; b4 += b4c[ls];
      float nrm = (float)(c*C + ls + 1);
      sa_s[ls] = sigmoidf_(b3/nrm);
      float cso = b4/nrm; cso = fminf(1.f, fmaxf(-1.f, cso));
      essh[ls] = __expf(cso);
      facs[ls] = sis[ls]/nrm;
    }
  }
  __syncthreads();

  // ---- scale sqs in place (q_scaled) ----
  #pragma unroll
  for(int k=0;k<4;k++){
    int i = t + k*256;
    int row = i>>4, col4 = (i&15)*4;
    float4 v = *(const float4*)(sqs + row*SDT + col4);
    float f = facs[row];
    *(float4*)(sqs + row*SDT + col4) = make_float4(v.x*f, v.y*f, v.z*f, v.w*f);
  }
  // ---- publish es chunk sum f3 ----
  if(t < 32){
    float v = essh[t] + essh[t+32];
    #pragma unroll
    for(int o=16;o;o>>=1) v += __shfl_down_sync(0xffffffffu, v, o);
    if(t==0){ g_eb[pc] = v; __threadfence(); atomicExch(&g_f3[pc], 1); }
  }

  // ---- preload V into registers (hides global latency across L3 wait) ----
  float4 vreg[4];
  #pragma unroll
  for(int k=0;k<4;k++){
    int i = t + k*256;
    int row = i>>4, col4 = (i&15)*4;
    vreg[k] = *(const float4*)(Vb + (size_t)row*HD + col4);
  }

  // ---- L3 wait ----
  if(c > 0){
    if(t < c) spin_flag(&g_f3[p*NC + t]);
    __syncthreads();
    if(t == 0){ float s=0.f; for(int i=0;i<c;i++) s += __ldg(&g_eb[p*NC+i]); prefsh = s; }
  } else {
    if(t == 0) prefsh = 0.f;
  }
  __syncthreads();
  // comp scan within chunk
  { float xscan = 0.f;
    if(t < 64){
      xscan = essh[t];
      #pragma unroll
      for(int o=1;o<32;o<<=1){
        float y = __shfl_up_sync(0xffffffffu, xscan, o);
        if((t&31) >= o) xscan += y;
      }
      if(t==31) wtot0 = xscan;
    }
    __syncthreads();
    if(t < 64){
      float cum = prefsh + xscan + ((t>=32)? wtot0 : 0.f);
      comp[t] = essh[t]/cum * (float)(c*C + t + 1);
    }
  }
  __syncthreads();

  // ---- vss = V*comp (overwrites skT; all skT uses done) ----
  #pragma unroll
  for(int k=0;k<4;k++){
    int i = t + k*256;
    int row = i>>4, col4 = (i&15)*4;
    float f = comp[row];
    *(float4*)(vss + row*D + col4) = make_float4(vreg[k].x*f, vreg[k].y*f, vreg[k].z*f, vreg[k].w*f);
  }
  __syncthreads();

  // ---- vkv: chunk KV aggregate, publish f4 ----
  int d0 = 4*(t>>4), m0 = 4*(t&15);
  { ull acc[8];
    #pragma unroll
    for(int m=0;m<8;m++) acc[m]=0ull;
    #pragma unroll 8
    for(int j=0;j<C;j++){
      float4 sk4 = *(const float4*)(skr + j*D + d0);
      double2 va = *(const double2*)(vss + j*D + m0);
      ull v0=(ull)__double_as_longlong(va.x), v1=(ull)__double_as_longlong(va.y);
      #pragma unroll
      for(int dd=0;dd<4;dd++){
        float a = f4get(sk4, dd);
        ull a2 = pack2(a,a);
        fma2(acc[dd*2],   a2, v0);
        fma2(acc[dd*2+1], a2, v1);
      }
    }
    float* gkv = g_kv + (size_t)pc*D*D;
    #pragma unroll
    for(int dd=0;dd<4;dd++){
      float2 u0=unpack2(acc[dd*2]), u1=unpack2(acc[dd*2+1]);
      *(float4*)(gkv + (d0+dd)*D + m0) = make_float4(u0.x,u0.y,u1.x,u1.y);
    }
  }
  __threadfence(); __syncthreads();
  if(t==0) atomicExch(&g_f4[pc], 1);

  // ---- out-intra BEFORE the L4 wait (prefix-independent) ----
  ull acc[8];
  #pragma unroll
  for(int m=0;m<8;m++) acc[m]=0ull;
  { int nf = l0 >> 2;
    for(int ib=0; ib<nf; ib++){
      float4 st4[4]; double2 va[4];
      #pragma unroll
      for(int u=0;u<4;u++){
        int i = 4*ib+u;
        st4[u] = *(const float4*)(STs + i*SDT + l0);
        va[u]  = *(const double2*)(vss + i*D + m0);
      }
      #pragma unroll
      for(int u=0;u<4;u++){
        ull v0=(ull)__double_as_longlong(va[u].x), v1=(ull)__double_as_longlong(va[u].y);
        #pragma unroll
        for(int ll=0;ll<4;ll++){
          float s = f4get(st4[u], ll);
          ull s2 = pack2(s,s);
          fma2(acc[ll*2],   s2, v0);
          fma2(acc[ll*2+1], s2, v1);
        }
      }
    }
    { float4 st4[4]; double2 va[4];
      #pragma unroll
      for(int u=0;u<4;u++){
        int i = l0+u;
        st4[u] = *(const float4*)(STs + i*SDT + l0);
        va[u]  = *(const double2*)(vss + i*D + m0);
      }
      #pragma unroll
      for(int u=0;u<4;u++){
        ull v0=(ull)__double_as_longlong(va[u].x), v1=(ull)__double_as_longlong(va[u].y);
        #pragma unroll
        for(int ll=0;ll<4;ll++){
          float s = (u <= ll) ? f4get(st4[u], ll) : 0.f;
          ull s2 = pack2(s,s);
          fma2(acc[ll*2],   s2, v0);
          fma2(acc[ll*2+1], s2, v1);
        }
      }
    }
    #pragma unroll
    for(int ll=0;ll<4;ll++){
      float f = facs[l0+ll];
      ull f2 = pack2(f,f);
      acc[ll*2]   = mul2(acc[ll*2],   f2);
      acc[ll*2+1] = mul2(acc[ll*2+1], f2);
    }
  }

  // ---- L4 wait + build KV prefix into kvs (overwrites skr) ----
  if(c > 0){
    if(t < c) spin_flag(&g_f4[p*NC + t]);
    __syncthreads();
    float4 a0=make_float4(0,0,0,0), a1=a0, a2=a0, a3=a0;
    for(int i=0;i<c;i++){
      const float4* gkv = (const float4*)(g_kv + (size_t)(p*NC+i)*D*D);
      float4 w0 = __ldg(gkv + ((d0+0)*D + m0)/4);
      float4 w1 = __ldg(gkv + ((d0+1)*D + m0)/4);
      float4 w2 = __ldg(gkv + ((d0+2)*D + m0)/4);
      float4 w3 = __ldg(gkv + ((d0+3)*D + m0)/4);
      a0.x+=w0.x; a0.y+=w0.y; a0.z+=w0.z; a0.w+=w0.w;
      a1.x+=w1.x; a1.y+=w1.y; a1.z+=w1.z; a1.w+=w1.w;
      a2.x+=w2.x; a2.y+=w2.y; a2.z+=w2.z; a2.w+=w2.w;
      a3.x+=w3.x; a3.y+=w3.y; a3.z+=w3.z; a3.w+=w3.w;
    }
    __syncthreads();   // vkv-phase reads of skr are done before overwrite
    *(float4*)(kvs + (d0+0)*D + m0) = a0;
    *(float4*)(kvs + (d0+1)*D + m0) = a1;
    *(float4*)(kvs + (d0+2)*D + m0) = a2;
    *(float4*)(kvs + (d0+3)*D + m0) = a3;
  } else {
    __syncthreads();
    for(int i=t;i<D*D;i+=256) kvs[i] = 0.f;
  }
  __syncthreads();

  // ---- out-inter: q_scaled @ KVprefix, then store ----
  {
    #pragma unroll 4
    for(int dq=0; dq<D; dq+=4){
      float4 q4[4];
      #pragma unroll
      for(int ll=0;ll<4;ll++) q4[ll] = *(const float4*)(sqs + (l0+ll)*SDT + dq);
      #pragma unroll
      for(int du=0;du<4;du++){
        double2 ka = *(const double2*)(kvs + (dq+du)*D + m0);
        ull k0=(ull)__double_as_longlong(ka.x), k1=(ull)__double_as_longlong(ka.y);
        #pragma unroll
        for(int ll=0;ll<4;ll++){
          float qv = f4get(q4[ll], du);
          ull q2 = pack2(qv,qv);
          fma2(acc[ll*2],   q2, k0);
          fma2(acc[ll*2+1], q2, k1);
        }
      }
    }
    float* op = OUT + (size_t)(p>>3)*LHD + (size_t)c*C*HD + (size_t)(p&7)*D;
    #pragma unroll
    for(int ll=0;ll<4;ll++){
      float sa = sa_s[l0+ll];
      float2 a0=unpack2(acc[ll*2]), a1=unpack2(acc[ll*2+1]);
      *(float4*)(op + (size_t)(l0+ll)*HD + m0) =
        make_float4(a0.x*sa, a0.y*sa, a1.x*sa, a1.y*sa);
    }
  }
}

// ---------------- launch ----------------
extern "C" void kernel_launch(void* const* d_in, const int* in_sizes, int n_in,
                              void* d_out, int out_size){
  const float* Q = (const float*)d_in[0];
  const float* K = (const float*)d_in[1];
  const float* V = (const float*)d_in[2];
  float* OUT = (float*)d_out;

  const int SM_FUSED = (3*C*SDT + C*D)*sizeof(float);   // 68608
  cudaFuncSetAttribute(k_fused, cudaFuncAttributeMaxDynamicSharedMemorySize, SM_FUSED);

  k_reset<<<1, 512>>>();
  k_fused<<<dim3(NC, P), 256, SM_FUSED>>>(Q, K, V, OUT);
}

// round 15
// speedup vs baseline: 1.2232x; 1.0922x over previous
#include <cuda_runtime.h>
#include <math.h>
#include <stdint.h>

#define NB   2
#define L    2048
#define H    8
#define D    64
#define HD   512
#define LHD  1048576
#define P    16
#define C    64
#define NC   32
#define EPSF 1e-6f
#define SDT  68

// ---------------- scan-aggregate scratch + flags ----------------
__device__ float g_ks[P*NC*D], g_qs[P*NC*D];   // phase-1 chunk sums (sigmoid k/q)
__device__ float g_ko[P*NC*D], g_qi[P*NC*D];   // phase-2 chunk sums (k*so / q*si)
__device__ float g_eb[P*NC];                   // es chunk sums
__device__ float g_kv[P*NC*D*D];               // KV chunk sums
__device__ int   g_f1[P*NC], g_f2[P*NC], g_f3[P*NC], g_f4[P*NC];

typedef unsigned long long ull;
__device__ __forceinline__ ull pack2(float a, float b){
  ull r; asm("mov.b64 %0, {%1,%2};" : "=l"(r) : "f"(a), "f"(b)); return r;
}
__device__ __forceinline__ void fma2(ull &acc, ull a, ull b){
  asm("fma.rn.f32x2 %0, %1, %2, %0;" : "+l"(acc) : "l"(a), "l"(b));
}
__device__ __forceinline__ ull mul2(ull a, ull b){
  ull r; asm("mul.rn.f32x2 %0, %1, %2;" : "=l"(r) : "l"(a), "l"(b)); return r;
}
__device__ __forceinline__ float2 unpack2(ull v){
  float2 r; asm("mov.b64 {%0,%1}, %2;" : "=f"(r.x), "=f"(r.y) : "l"(v)); return r;
}
__device__ __forceinline__ float sigmoidf_(float x){ return 1.f/(1.f+__expf(-x)); }
__device__ __forceinline__ float f4get(const float4& v, int u){
  return (u==0)?v.x:(u==1)?v.y:(u==2)?v.z:v.w;
}
__device__ __forceinline__ float red4(float v){
  v += __shfl_xor_sync(0xffffffffu, v, 1);
  v += __shfl_xor_sync(0xffffffffu, v, 2);
  return v;
}
__device__ __forceinline__ int ld_acq(const int* p){
  int v; asm volatile("ld.global.acquire.gpu.b32 %0, [%1];" : "=r"(v) : "l"(p)); return v;
}
// release store: publishes all writes ordered-before (via the preceding
// __syncthreads) without the CCTL.IVALL L1-flush of __threadfence()
__device__ __forceinline__ void st_rel(int* p, int v){
  asm volatile("st.global.release.gpu.b32 [%0], %1;" :: "l"(p), "r"(v) : "memory");
}
__device__ __forceinline__ void spin_flag(const int* f){
  int it = 0;
  while(ld_acq(f) == 0){
    __nanosleep(it < 16 ? 32 : 256);
    it++;
  }
}

__global__ void k_reset(){
  int t = threadIdx.x;
  if(t < P*NC){ g_f1[t]=0; g_f2[t]=0; g_f3[t]=0; g_f4[t]=0; }
}

// ---------------- THE fused kernel (p = fast grid dim) ----------------
__global__ void __launch_bounds__(256,3) k_fused(const float* __restrict__ Q,
                                                 const float* __restrict__ K,
                                                 const float* __restrict__ V,
                                                 float* __restrict__ OUT){
  extern __shared__ float sm[];
  float* sqs = sm;             // sigmoid(q) [l][d] stride 68; scaled in place later
  float* skT = sm + C*SDT;     // sigmoid(k)^T [d][j] stride 68; reused as vss [j][m] s64
  float* STs = sm + 2*C*SDT;   // S^T [j][l] stride 68  (STs[j*68+l] = S[l][j])
  float* skr = sm + 3*C*SDT;   // sigmoid(k) rows [j][d] s64; reused as kvs [d][m] s64
  float* vss = skT;
  float* kvs = skr;
  __shared__ float rsk[C], rsq[C], d1s[C], d2s[C], b3c[C], b4c[C], sis[C], sos[C];
  __shared__ float kpre[D], qpre[D], kpre2[D], qpre2[D], facs[C], essh[C], sa_s[C], comp[C];
  __shared__ float prefsh, wtot0;

  int p = blockIdx.x, c = blockIdx.y, t = threadIdx.x;   // p FAST: wave1 = c<=27 for all p
  int pc = p*NC + c;
  const float* Qb = Q + (size_t)(p>>3)*LHD + (size_t)c*C*HD + (size_t)(p&7)*D;
  const float* Kb = K + (size_t)(p>>3)*LHD + (size_t)c*C*HD + (size_t)(p&7)*D;
  const float* Vb = V + (size_t)(p>>3)*LHD + (size_t)c*C*HD + (size_t)(p&7)*D;

  // ---- load tiles, sigmoid ----
  #pragma unroll
  for(int k=0;k<4;k++){
    int i = t + k*256;
    int row = i>>4, col4 = (i&15)*4;
    float4 q4 = *(const float4*)(Qb + (size_t)row*HD + col4);
    q4.x=sigmoidf_(q4.x); q4.y=sigmoidf_(q4.y); q4.z=sigmoidf_(q4.z); q4.w=sigmoidf_(q4.w);
    *(float4*)(sqs + row*SDT + col4) = q4;
    float4 k4 = *(const float4*)(Kb + (size_t)row*HD + col4);
    k4.x=sigmoidf_(k4.x); k4.y=sigmoidf_(k4.y); k4.z=sigmoidf_(k4.z); k4.w=sigmoidf_(k4.w);
    *(float4*)(skr + row*D + col4) = k4;
    skT[(col4  )*SDT + row] = k4.x;
    skT[(col4+1)*SDT + row] = k4.y;
    skT[(col4+2)*SDT + row] = k4.z;
    skT[(col4+3)*SDT + row] = k4.w;
  }
  __syncthreads();

  int ls = t>>2, gs = t&3;
  // ---- chunk sums, publish f1 EARLY ----
  { float a=0.f, b=0.f;
    #pragma unroll
    for(int u=0;u<16;u++){
      int j = 4*u + gs;
      a += skT[ls*SDT + j];
      b += sqs[j*SDT + ls];
    }
    a = red4(a); b = red4(b);
    if(gs==0){ g_ks[pc*D + ls] = a; g_qs[pc*D + ls] = b; }
  }
  __syncthreads();
  if(t==0) st_rel(&g_f1[pc], 1);

  // ---- row sums rsk/rsq (prefix-independent) ----
  { float rk=0.f, rq=0.f;
    #pragma unroll
    for(int u=0;u<16;u++){
      int d = 4*u + gs;
      rk += skT[d*SDT + ls];
    }
    #pragma unroll
    for(int u=0;u<4;u++){
      int dd = 16*gs + 4*u;
      float4 q4 = *(const float4*)(sqs + ls*SDT + dd);
      rq += q4.x+q4.y+q4.z+q4.w;
    }
    rk = red4(rk); rq = red4(rq);
    if(gs==0){ rsk[ls]=rk; rsq[ls]=rq; }
  }

  // ---- gram: 4l x 4j tiles -> STs (prefix-independent) ----
  int l0 = 4*(t>>4), j0 = 4*(t&15);
  { ull acc[8];
    #pragma unroll
    for(int m=0;m<8;m++) acc[m]=0ull;
    #pragma unroll 4
    for(int dq=0; dq<D; dq+=4){
      float4 q4[4];
      #pragma unroll
      for(int ll=0;ll<4;ll++) q4[ll] = *(const float4*)(sqs + (l0+ll)*SDT + dq);
      #pragma unroll
      for(int du=0;du<4;du++){
        double2 ka = *(const double2*)(skT + (dq+du)*SDT + j0);
        ull k0=(ull)__double_as_longlong(ka.x), k1=(ull)__double_as_longlong(ka.y);
        #pragma unroll
        for(int ll=0;ll<4;ll++){
          float qv = f4get(q4[ll], du);
          ull q2 = pack2(qv,qv);
          fma2(acc[ll*2],   q2, k0);
          fma2(acc[ll*2+1], q2, k1);
        }
      }
    }
    float vals[4][4];
    #pragma unroll
    for(int ll=0;ll<4;ll++){
      float2 a0=unpack2(acc[ll*2]), a1=unpack2(acc[ll*2+1]);
      vals[ll][0]=a0.x; vals[ll][1]=a0.y; vals[ll][2]=a1.x; vals[ll][3]=a1.y;
    }
    #pragma unroll
    for(int jj=0;jj<4;jj++)
      *(float4*)(STs + (j0+jj)*SDT + l0) =
        make_float4(vals[0][jj], vals[1][jj], vals[2][jj], vals[3][jj]);
  }
  __syncthreads();

  // ---- causal sums of S (prefix-independent) ----
  { float d1=0.f, d2=0.f;
    for(int i=gs; i<=ls; i+=4){
      d1 += STs[i*SDT + ls] + EPSF*rsk[i];   // S[ls][i]
      d2 += STs[ls*SDT + i] + EPSF*rsq[i];   // S[i][ls]
    }
    d1 = red4(d1); d2 = red4(d2);
    if(gs==0){ d1s[ls]=d1; d2s[ls]=d2; }
  }

  // ---- L1 wait (overlapped by gram+causal above) ----
  if(c > 0){
    if(t < c) spin_flag(&g_f1[p*NC + t]);
    __syncthreads();
    if(t < 64){ float a=0.f; for(int i=0;i<c;i++) a += __ldg(&g_ks[(p*NC+i)*D + t]); kpre[t]=a; }
    else if(t < 128){ int d=t-64; float a=0.f; for(int i=0;i<c;i++) a += __ldg(&g_qs[(p*NC+i)*D + d]); qpre[d]=a; }
  } else {
    if(t < 64) kpre[t]=0.f; else if(t < 128) qpre[t-64]=0.f;
  }
  __syncthreads();

  // ---- b1/b2 prefix dots -> si/so ----
  { float b1=0.f, b2=0.f;
    #pragma unroll
    for(int u=0;u<4;u++){
      int dd = 16*gs + 4*u;
      float4 q4 = *(const float4*)(sqs + ls*SDT + dd);
      b1 += (q4.x+EPSF)*(kpre[dd]+EPSF) + (q4.y+EPSF)*(kpre[dd+1]+EPSF)
          + (q4.z+EPSF)*(kpre[dd+2]+EPSF) + (q4.w+EPSF)*(kpre[dd+3]+EPSF);
    }
    #pragma unroll
    for(int u=0;u<16;u++){
      int d = 4*u + gs;
      float kv = skT[d*SDT + ls];
      b2 += (kv+EPSF)*(qpre[d]+EPSF);
    }
    b1 = red4(b1); b2 = red4(b2);
    if(gs==0){
      float nrm = (float)(c*C + ls + 1);
      sis[ls] = nrm/(b1 + d1s[ls]);
      sos[ls] = nrm/(b2 + d2s[ls]);
    }
  }
  __syncthreads();

  // ---- kso/qsi chunk sums, publish f2 ----
  { float a1=0.f, a2=0.f;
    #pragma unroll
    for(int u=0;u<16;u++){
      int j = 4*u + gs;
      a1 += skT[ls*SDT + j]*sos[j];
      a2 += sqs[j*SDT + ls]*sis[j];
    }
    a1 = red4(a1); a2 = red4(a2);
    if(gs==0){ g_ko[pc*D + ls] = a1; g_qi[pc*D + ls] = a2; }
  }
  __syncthreads();
  if(t==0) st_rel(&g_f2[pc], 1);

  // ---- conserved causal partials (prefix-independent; hides L2) ----
  { float b3=0.f, b4=0.f;
    for(int i=gs; i<=ls; i+=4){
      b3 += sos[i]*(STs[i*SDT + ls] + EPSF*rsk[i]);
      b4 += sis[i]*(STs[ls*SDT + i] + EPSF*rsq[i]);
    }
    b3 = red4(b3); b4 = red4(b4);
    if(gs==0){ b3c[ls]=b3; b4c[ls]=b4; }
  }

  // ---- L2 wait ----
  if(c > 0){
    if(t < c) spin_flag(&g_f2[p*NC + t]);
    __syncthreads();
    if(t < 64){ float a=0.f; for(int i=0;i<c;i++) a += __ldg(&g_ko[(p*NC+i)*D + t]); kpre2[t]=a; }
    else if(t < 128){ int d=t-64; float a=0.f; for(int i=0;i<c;i++) a += __ldg(&g_qi[(p*NC+i)*D + d]); qpre2[d]=a; }
  } else {
    if(t < 64) kpre2[t]=0.f; else if(t < 128) qpre2[t-64]=0.f;
  }
  __syncthreads();

  // ---- finish conserved: sa, es, q-scale factor ----
  { float b3=0.f, b4=0.f;
    #pragma unroll
    for(int u=0;u<4;u++){
      int dd = 16*gs + 4*u;
      float4 q4 = *(const float4*)(sqs + ls*SDT + dd);
      b3 += (q4.x+EPSF)*(kpre2[dd]+EPSF) + (q4.y+EPSF)*(kpre2[dd+1]+EPSF)
          + (q4.z+EPSF)*(kpre2[dd+2]+EPSF) + (q4.w+EPSF)*(kpre2[dd+3]+EPSF);
    }
    #pragma unroll
    for(int u=0;u<16;u++){
      int d = 4*u + gs;
      float kv = skT[d*SDT + ls];
      b4 += (kv+EPSF)*(qpre2[d]+EPSF);
    }
    b3 = red4(b3); b4 = red4(b4);
    if(gs==0){
      b3 += b3c[ls]; b4 += b4c[ls];
      float nrm = (float)(c*C + ls + 1);
      sa_s[ls] = sigmoidf_(b3/nrm);
      float cso = b4/nrm; cso = fminf(1.f, fmaxf(-1.f, cso));
      essh[ls] = __expf(cso);
      facs[ls] = sis[ls]/nrm;
    }
  }
  __syncthreads();

  // ---- scale sqs in place (q_scaled) ----
  #pragma unroll
  for(int k=0;k<4;k++){
    int i = t + k*256;
    int row = i>>4, col4 = (i&15)*4;
    float4 v = *(const float4*)(sqs + row*SDT + col4);
    float f = facs[row];
    *(float4*)(sqs + row*SDT + col4) = make_float4(v.x*f, v.y*f, v.z*f, v.w*f);
  }
  // ---- publish es chunk sum f3 (t0 wrote it; release orders the pair) ----
  if(t < 32){
    float v = essh[t] + essh[t+32];
    #pragma unroll
    for(int o=16;o;o>>=1) v += __shfl_down_sync(0xffffffffu, v, o);
    if(t==0){ g_eb[pc] = v; st_rel(&g_f3[pc], 1); }
  }

  // ---- preload V into registers (hides global latency across L3 wait) ----
  float4 vreg[4];
  #pragma unroll
  for(int k=0;k<4;k++){
    int i = t + k*256;
    int row = i>>4, col4 = (i&15)*4;
    vreg[k] = *(const float4*)(Vb + (size_t)row*HD + col4);
  }

  // ---- L3 wait ----
  if(c > 0){
    if(t < c) spin_flag(&g_f3[p*NC + t]);
    __syncthreads();
    if(t == 0){ float s=0.f; for(int i=0;i<c;i++) s += __ldg(&g_eb[p*NC+i]); prefsh = s; }
  } else {
    if(t == 0) prefsh = 0.f;
  }
  __syncthreads();
  // comp scan within chunk
  { float xscan = 0.f;
    if(t < 64){
      xscan = essh[t];
      #pragma unroll
      for(int o=1;o<32;o<<=1){
        float y = __shfl_up_sync(0xffffffffu, xscan, o);
        if((t&31) >= o) xscan += y;
      }
      if(t==31) wtot0 = xscan;
    }
    __syncthreads();
    if(t < 64){
      float cum = prefsh + xscan + ((t>=32)? wtot0 : 0.f);
      comp[t] = essh[t]/cum * (float)(c*C + t + 1);
    }
  }
  __syncthreads();

  // ---- vss = V*comp (overwrites skT; all skT uses done) ----
  #pragma unroll
  for(int k=0;k<4;k++){
    int i = t + k*256;
    int row = i>>4, col4 = (i&15)*4;
    float f = comp[row];
    *(float4*)(vss + row*D + col4) = make_float4(vreg[k].x*f, vreg[k].y*f, vreg[k].z*f, vreg[k].w*f);
  }
  __syncthreads();

  // ---- vkv: chunk KV aggregate, publish f4 ----
  int d0 = 4*(t>>4), m0 = 4*(t&15);
  { ull acc[8];
    #pragma unroll
    for(int m=0;m<8;m++) acc[m]=0ull;
    #pragma unroll 8
    for(int j=0;j<C;j++){
      float4 sk4 = *(const float4*)(skr + j*D + d0);
      double2 va = *(const double2*)(vss + j*D + m0);
      ull v0=(ull)__double_as_longlong(va.x), v1=(ull)__double_as_longlong(va.y);
      #pragma unroll
      for(int dd=0;dd<4;dd++){
        float a = f4get(sk4, dd);
        ull a2 = pack2(a,a);
        fma2(acc[dd*2],   a2, v0);
        fma2(acc[dd*2+1], a2, v1);
      }
    }
    float* gkv = g_kv + (size_t)pc*D*D;
    #pragma unroll
    for(int dd=0;dd<4;dd++){
      float2 u0=unpack2(acc[dd*2]), u1=unpack2(acc[dd*2+1]);
      *(float4*)(gkv + (d0+dd)*D + m0) = make_float4(u0.x,u0.y,u1.x,u1.y);
    }
  }
  __syncthreads();
  if(t==0) st_rel(&g_f4[pc], 1);

  // ---- out-intra BEFORE the L4 wait (prefix-independent) ----
  ull acc[8];
  #pragma unroll
  for(int m=0;m<8;m++) acc[m]=0ull;
  { int nf = l0 >> 2;
    for(int ib=0; ib<nf; ib++){
      float4 st4[4]; double2 va[4];
      #pragma unroll
      for(int u=0;u<4;u++){
        int i = 4*ib+u;
        st4[u] = *(const float4*)(STs + i*SDT + l0);
        va[u]  = *(const double2*)(vss + i*D + m0);
      }
      #pragma unroll
      for(int u=0;u<4;u++){
        ull v0=(ull)__double_as_longlong(va[u].x), v1=(ull)__double_as_longlong(va[u].y);
        #pragma unroll
        for(int ll=0;ll<4;ll++){
          float s = f4get(st4[u], ll);
          ull s2 = pack2(s,s);
          fma2(acc[ll*2],   s2, v0);
          fma2(acc[ll*2+1], s2, v1);
        }
      }
    }
    { float4 st4[4]; double2 va[4];
      #pragma unroll
      for(int u=0;u<4;u++){
        int i = l0+u;
        st4[u] = *(const float4*)(STs + i*SDT + l0);
        va[u]  = *(const double2*)(vss + i*D + m0);
      }
      #pragma unroll
      for(int u=0;u<4;u++){
        ull v0=(ull)__double_as_longlong(va[u].x), v1=(ull)__double_as_longlong(va[u].y);
        #pragma unroll
        for(int ll=0;ll<4;ll++){
          float s = (u <= ll) ? f4get(st4[u], ll) : 0.f;
          ull s2 = pack2(s,s);
          fma2(acc[ll*2],   s2, v0);
          fma2(acc[ll*2+1], s2, v1);
        }
      }
    }
    #pragma unroll
    for(int ll=0;ll<4;ll++){
      float f = facs[l0+ll];
      ull f2 = pack2(f,f);
      acc[ll*2]   = mul2(acc[ll*2],   f2);
      acc[ll*2+1] = mul2(acc[ll*2+1], f2);
    }
  }

  // ---- L4 wait + build KV prefix into kvs (overwrites skr) ----
  if(c > 0){
    if(t < c) spin_flag(&g_f4[p*NC + t]);
    __syncthreads();
    float4 a0=make_float4(0,0,0,0), a1=a0, a2=a0, a3=a0;
    for(int i=0;i<c;i++){
      const float4* gkv = (const float4*)(g_kv + (size_t)(p*NC+i)*D*D);
      float4 w0 = __ldg(gkv + ((d0+0)*D + m0)/4);
      float4 w1 = __ldg(gkv + ((d0+1)*D + m0)/4);
      float4 w2 = __ldg(gkv + ((d0+2)*D + m0)/4);
      float4 w3 = __ldg(gkv + ((d0+3)*D + m0)/4);
      a0.x+=w0.x; a0.y+=w0.y; a0.z+=w0.z; a0.w+=w0.w;
      a1.x+=w1.x; a1.y+=w1.y; a1.z+=w1.z; a1.w+=w1.w;
      a2.x+=w2.x; a2.y+=w2.y; a2.z+=w2.z; a2.w+=w2.w;
      a3.x+=w3.x; a3.y+=w3.y; a3.z+=w3.z; a3.w+=w3.w;
    }
    __syncthreads();   // vkv-phase reads of skr are done before overwrite
    *(float4*)(kvs + (d0+0)*D + m0) = a0;
    *(float4*)(kvs + (d0+1)*D + m0) = a1;
    *(float4*)(kvs + (d0+2)*D + m0) = a2;
    *(float4*)(kvs + (d0+3)*D + m0) = a3;
  } else {
    __syncthreads();
    for(int i=t;i<D*D;i+=256) kvs[i] = 0.f;
  }
  __syncthreads();

  // ---- out-inter: q_scaled @ KVprefix, then store ----
  {
    #pragma unroll 4
    for(int dq=0; dq<D; dq+=4){
      float4 q4[4];
      #pragma unroll
      for(int ll=0;ll<4;ll++) q4[ll] = *(const float4*)(sqs + (l0+ll)*SDT + dq);
      #pragma unroll
      for(int du=0;du<4;du++){
        double2 ka = *(const double2*)(kvs + (dq+du)*D + m0);
        ull k0=(ull)__double_as_longlong(ka.x), k1=(ull)__double_as_longlong(ka.y);
        #pragma unroll
        for(int ll=0;ll<4;ll++){
          float qv = f4get(q4[ll], du);
          ull q2 = pack2(qv,qv);
          fma2(acc[ll*2],   q2, k0);
          fma2(acc[ll*2+1], q2, k1);
        }
      }
    }
    float* op = OUT + (size_t)(p>>3)*LHD + (size_t)c*C*HD + (size_t)(p&7)*D;
    #pragma unroll
    for(int ll=0;ll<4;ll++){
      float sa = sa_s[l0+ll];
      float2 a0=unpack2(acc[ll*2]), a1=unpack2(acc[ll*2+1]);
      *(float4*)(op + (size_t)(l0+ll)*HD + m0) =
        make_float4(a0.x*sa, a0.y*sa, a1.x*sa, a1.y*sa);
    }
  }
}

// ---------------- launch ----------------
extern "C" void kernel_launch(void* const* d_in, const int* in_sizes, int n_in,
                              void* d_out, int out_size){
  const float* Q = (const float*)d_in[0];
  const float* K = (const float*)d_in[1];
  const float* V = (const float*)d_in[2];
  float* OUT = (float*)d_out;

  const int SM_FUSED = (3*C*SDT + C*D)*sizeof(float);   // 68608
  cudaFuncSetAttribute(k_fused, cudaFuncAttributeMaxDynamicSharedMemorySize, SM_FUSED);

  k_reset<<<1, 512>>>();
  k_fused<<<dim3(P, NC), 256, SM_FUSED>>>(Q, K, V, OUT);
}